// round 4
// baseline (speedup 1.0000x reference)
#include <cuda_runtime.h>

// Problem constants
#define H_   128
#define W_   128
#define C_   32
#define B_   4
#define OH_  120
#define OW_  120
#define OCH_ 100
#define F_   64

__device__ float g_offbuf[(size_t)B_ * OH_ * OW_ * OCH_];

// ---- packed f32x2 helpers (sm_103a FFMA2 path) ----------------------------
typedef unsigned long long u64t;

__device__ __forceinline__ u64t ffma2(u64t a, u64t b, u64t c) {
    u64t d;
    asm("fma.rn.f32x2 %0, %1, %2, %3;" : "=l"(d) : "l"(a), "l"(b), "l"(c));
    return d;
}
__device__ __forceinline__ u64t fmul2(u64t a, u64t b) {
    u64t d;
    asm("mul.rn.f32x2 %0, %1, %2;" : "=l"(d) : "l"(a), "l"(b));
    return d;
}
__device__ __forceinline__ u64t dup2(float x) {
    u64t d; unsigned xi = __float_as_uint(x);
    asm("mov.b64 %0, {%1, %1};" : "=l"(d) : "r"(xi));
    return d;
}
__device__ __forceinline__ float2 up2(u64t v) {
    float2 f;
    asm("mov.b64 {%0, %1}, %2;" : "=f"(f.x), "=f"(f.y) : "l"(v));
    return f;
}
union f4u { float4 f; ulonglong2 u; };

// ---------------------------------------------------------------------------
// Kernel A: dense dilated 5x5 conv -> 100 offset channels.
// Tile 8y x 8x = 64 px, 200 threads (tm=ch-quad 0..24, tn=px-col 0..7),
// thread tile 4ch x 8px. Patch in smem (col-stride 36 -> conflict-free
// per-c broadcast reads). Weights read directly from global via __ldg
// (L1/L2-resident, 25 distinct 16B chunks/warp = 4-wavefront minimum).
// ONE __syncthreads total.
// ---------------------------------------------------------------------------
#define PCOL 36
__global__ __launch_bounds__(200, 3)
void offset_conv_kernel(const float* __restrict__ vol,
                        const float* __restrict__ w_off,
                        const float* __restrict__ b_off)
{
    __shared__ float patch[16 * 16 * PCOL];  // 36 KB

    const int tid = threadIdx.x;
    const int ox0 = blockIdx.x * 8;
    const int oy0 = blockIdx.y * 8;
    const int b   = blockIdx.z;

    // Load patch: 16 rows x 16 cols x 32 ch (gmem-coalesced float4 reads)
    for (int idx = tid; idx < 2048; idx += 200) {
        int row = idx >> 7;
        int rem = idx & 127;
        int col = rem >> 3;
        int c4  = rem & 7;
        const float4 v = *reinterpret_cast<const float4*>(
            vol + ((size_t)((b * H_ + oy0 + row) * W_ + ox0 + col)) * C_ + 4 * c4);
        *reinterpret_cast<float4*>(&patch[(row * 16 + col) * PCOL + 4 * c4]) = v;
    }
    __syncthreads();

    const int tm = tid % 25;   // ch quad: ch0 = 4*tm
    const int tn = tid / 25;   // px col:  tx = tn

    u64t acc2[2][8];
#pragma unroll
    for (int i = 0; i < 2; ++i)
#pragma unroll
        for (int jj = 0; jj < 8; ++jj) acc2[i][jj] = 0ull;

    const float* wbase = w_off + 4 * tm;

    for (int k = 0; k < 25; ++k) {
        const int fy2 = (k / 5) * 2, fx2 = (k % 5) * 2;
        const float* pb = &patch[(fy2 * 16 + tn + fx2) * PCOL];
        const float* wk = wbase + k * 3200;
#pragma unroll 8
        for (int c = 0; c < 32; ++c) {
            f4u Av; Av.f = __ldg(reinterpret_cast<const float4*>(wk + c * 100));
            u64t ap[2] = {Av.u.x, Av.u.y};
            u64t bp[8];
#pragma unroll
            for (int jj = 0; jj < 8; ++jj) bp[jj] = dup2(pb[jj * (16 * PCOL) + c]);
#pragma unroll
            for (int i = 0; i < 2; ++i)
#pragma unroll
                for (int jj = 0; jj < 8; ++jj)
                    acc2[i][jj] = ffma2(ap[i], bp[jj], acc2[i][jj]);
        }
    }

    const int ch0 = 4 * tm;
    const float bo0 = __ldg(b_off + ch0),     bo1 = __ldg(b_off + ch0 + 1);
    const float bo2 = __ldg(b_off + ch0 + 2), bo3 = __ldg(b_off + ch0 + 3);
#pragma unroll
    for (int jj = 0; jj < 8; ++jj) {
        int oy = oy0 + jj, ox = ox0 + tn;
        float2 lo = up2(acc2[0][jj]);
        float2 hi = up2(acc2[1][jj]);
        float4 r = make_float4(lo.x + bo0, lo.y + bo1, hi.x + bo2, hi.y + bo3);
        *reinterpret_cast<float4*>(
            &g_offbuf[((size_t)((b * OH_ + oy) * OW_ + ox)) * OCH_ + ch0]) = r;
    }
}

// ---------------------------------------------------------------------------
// Kernel B: deformable gather + grouped conv.
// Tile 8y x 8x = 64 px, 128 threads. Double-buffered sample smem -> ONE
// __syncthreads per tap. Weights read directly from global (__ldg, 8 KB/tap,
// L1-resident, 8 distinct 16B chunks/warp = 1 wavefront).
// ---------------------------------------------------------------------------
#define SS_P   36
#define SS_G   2320

__global__ __launch_bounds__(128, 5)
void dcn_kernel(const float* __restrict__ vol,
                const float* __restrict__ w_dcn,
                const float* __restrict__ b_dcn,
                float* __restrict__ out)
{
    __shared__ float Ss[2][2 * SS_G];   // double-buffered sampled [g][p][c] (37 KB)

    const int tid  = threadIdx.x;
    const int lane = tid & 31;
    const int warp = tid >> 5;
    const int ox0 = blockIdx.x * 8;
    const int oy0 = blockIdx.y * 8;
    const int b   = blockIdx.z;

    const int om  = tid & 7;
    const int pn  = tid >> 3;
    const int myg = om >> 2;

    const int q = lane >> 3;
    const int j = lane & 7;
    const int sBase = warp * 32;

    const float* volb = vol + (size_t)b * (H_ * W_ * C_);
    const float* offb = g_offbuf + ((size_t)(b * OH_ + oy0) * OW_ + ox0) * OCH_;
    const float* wbase = w_dcn + om * 8;

    u64t acc2[4][4];
#pragma unroll
    for (int i = 0; i < 4; ++i)
#pragma unroll
        for (int jj = 0; jj < 4; ++jj) acc2[i][jj] = 0ull;

    for (int k = 0; k < 25; ++k) {
        float* Sb = Ss[k & 1];

        const int fy = k / 5, fx = k - fy * 5;
        const float dky = (float)((fy - 2) * 2);
        const float dkx = (float)((fx - 2) * 2);

        // Gather this tap's 128 samples into Sb (warp-cooperative, full-line LDG.128)
#pragma unroll
        for (int pass = 0; pass < 8; ++pass) {
            int s = sBase + pass * 4 + q;
            int p = s & 63, g = s >> 6;
            int pyi = p >> 3, pxi = p & 7;

            const float* op = offb + (pyi * OW_ + pxi) * OCH_ + k * 4 + g;
            float offy = op[0];
            float offx = op[2];

            float py = (float)(oy0 + pyi + 4) + dky + offy;
            float px = (float)(ox0 + pxi + 4) + dkx + offx;
            py = fminf(fmaxf(py, 0.0f), 127.0f);
            px = fminf(fmaxf(px, 0.0f), 127.0f);
            float y0f = fminf(floorf(py), 126.0f);
            float x0f = fminf(floorf(px), 126.0f);
            float wy = py - y0f, wx = px - x0f;
            int y0 = (int)y0f, x0 = (int)x0f;

            const float4* r0 = reinterpret_cast<const float4*>(
                volb + ((size_t)(y0 * W_ + x0)) * C_);
            f4u L0, L1, L2, L3;
            L0.f = r0[j];
            L1.f = r0[j + 8];
            L2.f = r0[j + 1024];
            L3.f = r0[j + 1032];

            u64t c00p = dup2((1.0f - wy) * (1.0f - wx));
            u64t c01p = dup2((1.0f - wy) * wx);
            u64t c10p = dup2(wy * (1.0f - wx));
            u64t c11p = dup2(wy * wx);

            ulonglong2 sv;
            sv.x = ffma2(L0.u.x, c00p, ffma2(L1.u.x, c01p,
                       ffma2(L2.u.x, c10p, fmul2(L3.u.x, c11p))));
            sv.y = ffma2(L0.u.y, c00p, ffma2(L1.u.y, c01p,
                       ffma2(L2.u.y, c10p, fmul2(L3.u.y, c11p))));

            *reinterpret_cast<ulonglong2*>(&Sb[g * SS_G + p * SS_P + j * 4]) = sv;
        }
        __syncthreads();

        // GEMM over C=32; weights direct from global (L1 broadcast)
        const float* Sg = Sb + myg * SS_G;
        const float* wk = wbase + k * 2048;
#pragma unroll 8
        for (int c = 0; c < 32; ++c) {
            f4u A0, A1;
            A0.f = __ldg(reinterpret_cast<const float4*>(wk + c * 64));
            A1.f = __ldg(reinterpret_cast<const float4*>(wk + c * 64 + 4));
            u64t ap[4] = {A0.u.x, A0.u.y, A1.u.x, A1.u.y};
            u64t bp[4];
            bp[0] = dup2(Sg[(pn     ) * SS_P + c]);
            bp[1] = dup2(Sg[(pn + 16) * SS_P + c]);
            bp[2] = dup2(Sg[(pn + 32) * SS_P + c]);
            bp[3] = dup2(Sg[(pn + 48) * SS_P + c]);
#pragma unroll
            for (int i = 0; i < 4; ++i)
#pragma unroll
                for (int jj = 0; jj < 4; ++jj)
                    acc2[i][jj] = ffma2(ap[i], bp[jj], acc2[i][jj]);
        }
    }

    const int o0 = om * 8;
    float bo[8];
#pragma unroll
    for (int i = 0; i < 8; ++i) bo[i] = __ldg(b_dcn + o0 + i);
#pragma unroll
    for (int jj = 0; jj < 4; ++jj) {
        int p  = pn + jj * 16;
        int oy = oy0 + (p >> 3), ox = ox0 + (p & 7);
        float* opx = out + ((size_t)((b * OH_ + oy) * OW_ + ox)) * F_ + o0;
        float2 p0 = up2(acc2[0][jj]);
        float2 p1 = up2(acc2[1][jj]);
        float2 p2 = up2(acc2[2][jj]);
        float2 p3 = up2(acc2[3][jj]);
        float4 r0 = make_float4(p0.x + bo[0], p0.y + bo[1], p1.x + bo[2], p1.y + bo[3]);
        float4 r1 = make_float4(p2.x + bo[4], p2.y + bo[5], p3.x + bo[6], p3.y + bo[7]);
        *reinterpret_cast<float4*>(opx)     = r0;
        *reinterpret_cast<float4*>(opx + 4) = r1;
    }
}

// ---------------------------------------------------------------------------
extern "C" void kernel_launch(void* const* d_in, const int* in_sizes, int n_in,
                              void* d_out, int out_size)
{
    const float* vol   = (const float*)d_in[0];
    const float* w_off = (const float*)d_in[1];
    const float* b_off = (const float*)d_in[2];
    const float* w_dcn = (const float*)d_in[3];
    const float* b_dcn = (const float*)d_in[4];
    float* out = (float*)d_out;

    dim3 gA(OW_ / 8, OH_ / 8, B_);   // (15, 15, 4)
    offset_conv_kernel<<<gA, 200>>>(vol, w_off, b_off);

    dim3 gB(OW_ / 8, OH_ / 8, B_);   // (15, 15, 4)
    dcn_kernel<<<gB, 128>>>(vol, w_dcn, b_dcn, out);
}

// round 5
// speedup vs baseline: 1.4658x; 1.4658x over previous
#include <cuda_runtime.h>

// Problem constants
#define H_   128
#define W_   128
#define C_   32
#define B_   4
#define OH_  120
#define OW_  120
#define OCH_ 100
#define F_   64

__device__ float g_offbuf[(size_t)B_ * OH_ * OW_ * OCH_];

// ---- packed f32x2 helpers (sm_103a FFMA2 path) ----------------------------
typedef unsigned long long u64t;

__device__ __forceinline__ u64t ffma2(u64t a, u64t b, u64t c) {
    u64t d;
    asm("fma.rn.f32x2 %0, %1, %2, %3;" : "=l"(d) : "l"(a), "l"(b), "l"(c));
    return d;
}
__device__ __forceinline__ u64t fmul2(u64t a, u64t b) {
    u64t d;
    asm("mul.rn.f32x2 %0, %1, %2;" : "=l"(d) : "l"(a), "l"(b));
    return d;
}
__device__ __forceinline__ u64t dup2(float x) {
    u64t d; unsigned xi = __float_as_uint(x);
    asm("mov.b64 %0, {%1, %1};" : "=l"(d) : "r"(xi));
    return d;
}
__device__ __forceinline__ float2 up2(u64t v) {
    float2 f;
    asm("mov.b64 {%0, %1}, %2;" : "=f"(f.x), "=f"(f.y) : "l"(v));
    return f;
}
union f4u { float4 f; ulonglong2 u; };

// ---------------------------------------------------------------------------
// Kernel A: dense dilated 5x5 conv -> 100 offset channels. (unchanged from R4,
// measured ~235us) Tile 8x8 px, 200 threads, thread tile 4ch x 8px, patch in
// smem stride-36, weights via __ldg, one __syncthreads total.
// ---------------------------------------------------------------------------
#define PCOL 36
__global__ __launch_bounds__(200, 3)
void offset_conv_kernel(const float* __restrict__ vol,
                        const float* __restrict__ w_off,
                        const float* __restrict__ b_off)
{
    __shared__ float patch[16 * 16 * PCOL];  // 36 KB

    const int tid = threadIdx.x;
    const int ox0 = blockIdx.x * 8;
    const int oy0 = blockIdx.y * 8;
    const int b   = blockIdx.z;

    for (int idx = tid; idx < 2048; idx += 200) {
        int row = idx >> 7;
        int rem = idx & 127;
        int col = rem >> 3;
        int c4  = rem & 7;
        const float4 v = *reinterpret_cast<const float4*>(
            vol + ((size_t)((b * H_ + oy0 + row) * W_ + ox0 + col)) * C_ + 4 * c4);
        *reinterpret_cast<float4*>(&patch[(row * 16 + col) * PCOL + 4 * c4]) = v;
    }
    __syncthreads();

    const int tm = tid % 25;
    const int tn = tid / 25;

    u64t acc2[2][8];
#pragma unroll
    for (int i = 0; i < 2; ++i)
#pragma unroll
        for (int jj = 0; jj < 8; ++jj) acc2[i][jj] = 0ull;

    const float* wbase = w_off + 4 * tm;

    for (int k = 0; k < 25; ++k) {
        const int fy2 = (k / 5) * 2, fx2 = (k % 5) * 2;
        const float* pb = &patch[(fy2 * 16 + tn + fx2) * PCOL];
        const float* wk = wbase + k * 3200;
#pragma unroll 8
        for (int c = 0; c < 32; ++c) {
            f4u Av; Av.f = __ldg(reinterpret_cast<const float4*>(wk + c * 100));
            u64t ap[2] = {Av.u.x, Av.u.y};
            u64t bp[8];
#pragma unroll
            for (int jj = 0; jj < 8; ++jj) bp[jj] = dup2(pb[jj * (16 * PCOL) + c]);
#pragma unroll
            for (int i = 0; i < 2; ++i)
#pragma unroll
                for (int jj = 0; jj < 8; ++jj)
                    acc2[i][jj] = ffma2(ap[i], bp[jj], acc2[i][jj]);
        }
    }

    const int ch0 = 4 * tm;
    const float bo0 = __ldg(b_off + ch0),     bo1 = __ldg(b_off + ch0 + 1);
    const float bo2 = __ldg(b_off + ch0 + 2), bo3 = __ldg(b_off + ch0 + 3);
#pragma unroll
    for (int jj = 0; jj < 8; ++jj) {
        int oy = oy0 + jj, ox = ox0 + tn;
        float2 lo = up2(acc2[0][jj]);
        float2 hi = up2(acc2[1][jj]);
        float4 r = make_float4(lo.x + bo0, lo.y + bo1, hi.x + bo2, hi.y + bo3);
        *reinterpret_cast<float4*>(
            &g_offbuf[((size_t)((b * OH_ + oy) * OW_ + ox)) * OCH_ + ch0]) = r;
    }
}

// ---------------------------------------------------------------------------
// Kernel B v4: deformable gather + grouped conv.
// Tile 8y x 8x = 64 px, 128 threads (4 warps).
// Warp w owns outs [16w, 16w+16) (deform group w>>1); lane owns px pair
// {2*lane, 2*lane+1}. Per c-step: 4 uniform LDS.128 (broadcast, 1 wf) for
// weights + 1 LDS.64 (2 wf) for the px pair -> 6 wf per 16 FFMA2.
// Samples stored [g][c][px] stride 66; Ss and wks double-buffered ->
// ONE __syncthreads per tap.
// ---------------------------------------------------------------------------
#define SS_C   66                  // c-row stride (floats)
#define SS_G2  (32 * SS_C + 8)     // 2120: group stride
#define SS_BUF (2 * SS_G2)         // 4240 floats per buffer

__global__ __launch_bounds__(128, 4)
void dcn_kernel(const float* __restrict__ vol,
                const float* __restrict__ w_dcn,
                const float* __restrict__ b_dcn,
                float* __restrict__ out)
{
    __shared__ __align__(16) float Ss[2][SS_BUF];    // 33.9 KB
    __shared__ __align__(16) float wks[2][2048];     // 16 KB

    const int tid  = threadIdx.x;
    const int lane = tid & 31;
    const int warp = tid >> 5;
    const int ox0 = blockIdx.x * 8;
    const int oy0 = blockIdx.y * 8;
    const int b   = blockIdx.z;

    // GEMM roles: warp -> 16 outs, lane -> px pair
    const int o0  = warp * 16;
    const int myg = warp >> 1;

    // Gather roles: per pass, 4 samples x 8 lanes
    const int q = lane >> 3;
    const int j = lane & 7;
    const int sBase = warp * 32;

    const float* volb = vol + (size_t)b * (H_ * W_ * C_);
    const float* offb = g_offbuf + ((size_t)(b * OH_ + oy0) * OW_ + ox0) * OCH_;

    u64t acc2[8][2];   // [out-pair][px]
#pragma unroll
    for (int t = 0; t < 8; ++t) {
        acc2[t][0] = 0ull; acc2[t][1] = 0ull;
    }

    for (int k = 0; k < 25; ++k) {
        float* Sb = Ss[k & 1];
        float* Wb = wks[k & 1];

        // Stage this tap's weights (coalesced float4 copy, conflict-free STS)
        {
            const float4* wsrc = reinterpret_cast<const float4*>(w_dcn + k * 2048);
            float4* wdst = reinterpret_cast<float4*>(Wb);
#pragma unroll
            for (int i = 0; i < 4; ++i)
                wdst[tid + i * 128] = wsrc[tid + i * 128];
        }

        const int fy = k / 5, fx = k - fy * 5;
        const float dky = (float)((fy - 2) * 2);
        const float dkx = (float)((fx - 2) * 2);

        // Gather 128 samples (warp-cooperative, full-line LDG.128)
#pragma unroll
        for (int pass = 0; pass < 8; ++pass) {
            int s = sBase + pass * 4 + q;
            int p = s & 63, g = s >> 6;
            int pyi = p >> 3, pxi = p & 7;

            const float* op = offb + (pyi * OW_ + pxi) * OCH_ + k * 4 + g;
            float offy = op[0];
            float offx = op[2];

            float py = (float)(oy0 + pyi + 4) + dky + offy;
            float px = (float)(ox0 + pxi + 4) + dkx + offx;
            py = fminf(fmaxf(py, 0.0f), 127.0f);
            px = fminf(fmaxf(px, 0.0f), 127.0f);
            float y0f = fminf(floorf(py), 126.0f);
            float x0f = fminf(floorf(px), 126.0f);
            float wy = py - y0f, wx = px - x0f;
            int y0 = (int)y0f, x0 = (int)x0f;

            const float4* r0 = reinterpret_cast<const float4*>(
                volb + ((size_t)(y0 * W_ + x0)) * C_);
            f4u L0, L1, L2, L3;
            L0.f = r0[j];
            L1.f = r0[j + 8];
            L2.f = r0[j + 1024];
            L3.f = r0[j + 1032];

            u64t c00p = dup2((1.0f - wy) * (1.0f - wx));
            u64t c01p = dup2((1.0f - wy) * wx);
            u64t c10p = dup2(wy * (1.0f - wx));
            u64t c11p = dup2(wy * wx);

            ulonglong2 svu;
            svu.x = ffma2(L0.u.x, c00p, ffma2(L1.u.x, c01p,
                        ffma2(L2.u.x, c10p, fmul2(L3.u.x, c11p))));
            svu.y = ffma2(L0.u.y, c00p, ffma2(L1.u.y, c01p,
                        ffma2(L2.u.y, c10p, fmul2(L3.u.y, c11p))));
            float2 s01 = up2(svu.x);
            float2 s23 = up2(svu.y);

            // scatter channels 4j..4j+3 of sample p into [g][c][px]
            float* dstb = &Sb[g * SS_G2 + p];
            dstb[(4 * j    ) * SS_C] = s01.x;
            dstb[(4 * j + 1) * SS_C] = s01.y;
            dstb[(4 * j + 2) * SS_C] = s23.x;
            dstb[(4 * j + 3) * SS_C] = s23.y;
        }
        __syncthreads();

        // GEMM over C=32: uniform weight LDS.128 (broadcast) + LDS.64 samples
        const float* Sg = Sb + myg * SS_G2;
        const float* wo = Wb + o0;
#pragma unroll 8
        for (int c = 0; c < 32; ++c) {
            f4u W0, W1, W2, W3;
            W0.f = *reinterpret_cast<const float4*>(wo + c * 64);
            W1.f = *reinterpret_cast<const float4*>(wo + c * 64 + 4);
            W2.f = *reinterpret_cast<const float4*>(wo + c * 64 + 8);
            W3.f = *reinterpret_cast<const float4*>(wo + c * 64 + 12);
            u64t wp[8] = {W0.u.x, W0.u.y, W1.u.x, W1.u.y,
                          W2.u.x, W2.u.y, W3.u.x, W3.u.y};
            float2 sp = *reinterpret_cast<const float2*>(Sg + c * SS_C + 2 * lane);
            u64t b0 = dup2(sp.x);
            u64t b1 = dup2(sp.y);
#pragma unroll
            for (int t = 0; t < 8; ++t) {
                acc2[t][0] = ffma2(wp[t], b0, acc2[t][0]);
                acc2[t][1] = ffma2(wp[t], b1, acc2[t][1]);
            }
        }
    }

    // Epilogue: bias + stores. Thread writes 16 outs x 2 px.
    f4u B0, B1, B2, B3;
    B0.f = __ldg(reinterpret_cast<const float4*>(b_dcn + o0));
    B1.f = __ldg(reinterpret_cast<const float4*>(b_dcn + o0 + 4));
    B2.f = __ldg(reinterpret_cast<const float4*>(b_dcn + o0 + 8));
    B3.f = __ldg(reinterpret_cast<const float4*>(b_dcn + o0 + 12));
    float bo[16];
    {
        float2 t0 = up2(B0.u.x), t1 = up2(B0.u.y), t2 = up2(B1.u.x), t3 = up2(B1.u.y);
        float2 t4 = up2(B2.u.x), t5 = up2(B2.u.y), t6 = up2(B3.u.x), t7 = up2(B3.u.y);
        bo[0]=t0.x; bo[1]=t0.y; bo[2]=t1.x; bo[3]=t1.y;
        bo[4]=t2.x; bo[5]=t2.y; bo[6]=t3.x; bo[7]=t3.y;
        bo[8]=t4.x; bo[9]=t4.y; bo[10]=t5.x; bo[11]=t5.y;
        bo[12]=t6.x; bo[13]=t6.y; bo[14]=t7.x; bo[15]=t7.y;
    }
#pragma unroll
    for (int p = 0; p < 2; ++p) {
        int px = 2 * lane + p;
        int oy = oy0 + (px >> 3), ox = ox0 + (px & 7);
        float* opx = out + ((size_t)((b * OH_ + oy) * OW_ + ox)) * F_ + o0;
#pragma unroll
        for (int u = 0; u < 4; ++u) {
            float2 lo = up2(acc2[2 * u][p]);
            float2 hi = up2(acc2[2 * u + 1][p]);
            float4 r = make_float4(lo.x + bo[4 * u], lo.y + bo[4 * u + 1],
                                   hi.x + bo[4 * u + 2], hi.y + bo[4 * u + 3]);
            *reinterpret_cast<float4*>(opx + 4 * u) = r;
        }
    }
}

// ---------------------------------------------------------------------------
extern "C" void kernel_launch(void* const* d_in, const int* in_sizes, int n_in,
                              void* d_out, int out_size)
{
    const float* vol   = (const float*)d_in[0];
    const float* w_off = (const float*)d_in[1];
    const float* b_off = (const float*)d_in[2];
    const float* w_dcn = (const float*)d_in[3];
    const float* b_dcn = (const float*)d_in[4];
    float* out = (float*)d_out;

    dim3 gA(OW_ / 8, OH_ / 8, B_);   // (15, 15, 4)
    offset_conv_kernel<<<gA, 200>>>(vol, w_off, b_off);

    dim3 gB(OW_ / 8, OH_ / 8, B_);   // (15, 15, 4)
    dcn_kernel<<<gB, 128>>>(vol, w_dcn, b_dcn, out);
}